// round 1
// baseline (speedup 1.0000x reference)
#include <cuda_runtime.h>
#include <math.h>

// Problem constants
#define B_TOTAL  16384
#define F_S      48
#define T_S      512
#define N_LAYERS 16

// Tiling
#define ROWS     32
#define THREADS  256
#define NCTA     (B_TOTAL / ROWS)   // 512 CTAs

// ---------------- device scratch (no allocations allowed) ----------------
__device__ float2 g_R[B_TOTAL * T_S];          // R state, 64 MB (L2-resident)
__device__ float  g_partial[NCTA * T_S];       // per-CTA partial sums of |R|^2
__device__ float  g_gate[T_S];                 // gate vector g
__device__ float2 g_cs_tf[T_S * F_S];          // (cos,sin)/sqrt(T), [t][f] layout (phase-2 coalesced over f)
__device__ float2 g_cs_ft[F_S * T_S];          // (cos,sin)/sqrt(T), [f][t] layout (phase-4 coalesced over t)
__device__ float  g_scale[2];                  // [0] = 5/|max|, [1] = |max|/5
__device__ float  g_maxpart[256];

// ---------------- max reduction ----------------
__global__ void k_max1(const float* __restrict__ u, int n) {
    float m = -INFINITY;
    for (int i = blockIdx.x * blockDim.x + threadIdx.x; i < n; i += gridDim.x * blockDim.x)
        m = fmaxf(m, u[i]);
    __shared__ float sm[256];
    sm[threadIdx.x] = m;
    __syncthreads();
    for (int s = 128; s > 0; s >>= 1) {
        if (threadIdx.x < s) sm[threadIdx.x] = fmaxf(sm[threadIdx.x], sm[threadIdx.x + s]);
        __syncthreads();
    }
    if (threadIdx.x == 0) g_maxpart[blockIdx.x] = sm[0];
}

__global__ void k_max2() {
    __shared__ float sm[256];
    sm[threadIdx.x] = g_maxpart[threadIdx.x];
    __syncthreads();
    for (int s = 128; s > 0; s >>= 1) {
        if (threadIdx.x < s) sm[threadIdx.x] = fmaxf(sm[threadIdx.x], sm[threadIdx.x + s]);
        __syncthreads();
    }
    if (threadIdx.x == 0) {
        float m = fabsf(sm[0]);
        g_scale[0] = 5.0f / m;
        g_scale[1] = m / 5.0f;
    }
}

// ---------------- twiddle factors (exact phase via integer mod) ----------------
__global__ void k_tw() {
    int i = blockIdx.x * blockDim.x + threadIdx.x;
    if (i >= T_S * F_S) return;
    int t = i / F_S, f = i % F_S;
    int k = (f * t) % T_S;   // exact: cos(2*pi*f*t/T) periodic in T
    double ang = (double)k * (2.0 * M_PI / (double)T_S);
    double sc = 1.0 / sqrt((double)T_S);
    double s, c;
    sincos(ang, &s, &c);
    float2 v = make_float2((float)(c * sc), (float)(s * sc));
    g_cs_tf[t * F_S + f] = v;
    g_cs_ft[f * T_S + t] = v;
}

// ---------------- fused layer kernel ----------------
// Per layer n: H = R_{n-1} * g_{n-1} ; h = H @ dft ; z = u_s - h ;
//              Z = z @ idft ; R_n = H + Z ; partial sums of |R_n|^2
// first=1: H = 0 (layer 1), so z = u_s directly and phase 2 is skipped.
extern __shared__ float smem_raw[];

__global__ void __launch_bounds__(THREADS) k_layer(const float* __restrict__ u, int first) {
    float2* Hs = (float2*)smem_raw;            // ROWS * T_S
    float2* zs = Hs + ROWS * T_S;              // ROWS * F_S
    float*  gs = (float*)(zs + ROWS * F_S);    // T_S
    const int tid = threadIdx.x;
    const int b0  = blockIdx.x * ROWS;
    const float s_in = g_scale[0];

    // stage gate
    for (int i = tid; i < T_S; i += THREADS) gs[i] = first ? 0.0f : g_gate[i];
    __syncthreads();

    // ---- phase 1: H = R_prev * g_prev (or zero) ----
    if (first) {
        for (int i = tid; i < ROWS * T_S; i += THREADS) Hs[i] = make_float2(0.0f, 0.0f);
    } else {
        for (int i = tid; i < ROWS * T_S; i += THREADS) {
            int r = i >> 9, t = i & (T_S - 1);
            float2 R = g_R[(b0 + r) * T_S + t];
            float gv = gs[t];
            Hs[i] = make_float2(R.x * gv, R.y * gv);
        }
    }
    __syncthreads();

    // ---- phase 2+3: h = H @ dft (dft = (c,-s)); z = u_s - h ----
    {
        const int f  = tid & 63;    // 48 active lanes per 64
        const int rg = tid >> 6;    // 0..3
        if (first) {
            for (int i = tid; i < ROWS * F_S; i += THREADS) {
                int r = i / F_S, ff = i - r * F_S;
                float2 uv = ((const float2*)u)[(b0 + r) * F_S + ff];
                zs[i] = make_float2(uv.x * s_in, uv.y * s_in);
            }
        } else if (f < F_S) {
            float hr[ROWS / 4], hi[ROWS / 4];
#pragma unroll
            for (int j = 0; j < ROWS / 4; ++j) { hr[j] = 0.0f; hi[j] = 0.0f; }
#pragma unroll 4
            for (int t = 0; t < T_S; ++t) {
                float2 cs = g_cs_tf[t * F_S + f];
#pragma unroll
                for (int j = 0; j < ROWS / 4; ++j) {
                    float2 H = Hs[(rg + 4 * j) * T_S + t];   // warp-broadcast from smem
                    // h_re += Hre*c + Him*s ; h_im += Him*c - Hre*s
                    hr[j] = fmaf(H.x, cs.x, fmaf(H.y,  cs.y, hr[j]));
                    hi[j] = fmaf(H.y, cs.x, fmaf(-H.x, cs.y, hi[j]));
                }
            }
#pragma unroll
            for (int j = 0; j < ROWS / 4; ++j) {
                int r = rg + 4 * j;
                float2 uv = ((const float2*)u)[(b0 + r) * F_S + f];
                zs[r * F_S + f] = make_float2(uv.x * s_in - hr[j], uv.y * s_in - hi[j]);
            }
        }
    }
    __syncthreads();

    // ---- phase 4: Z = z @ idft (idft = (c,+s)); R = H + Z; partial sums ----
    for (int t = tid; t < T_S; t += THREADS) {
        float ssum = 0.0f;
        for (int rc = 0; rc < ROWS; rc += 8) {
            float ar[8], ai[8];
#pragma unroll
            for (int k = 0; k < 8; ++k) { ar[k] = 0.0f; ai[k] = 0.0f; }
#pragma unroll 8
            for (int f = 0; f < F_S; ++f) {
                float2 cs = g_cs_ft[f * T_S + t];   // coalesced over t within warp
#pragma unroll
                for (int k = 0; k < 8; ++k) {
                    float2 z = zs[(rc + k) * F_S + f];   // warp-broadcast from smem
                    ar[k] = fmaf(z.x, cs.x, fmaf(-z.y, cs.y, ar[k]));
                    ai[k] = fmaf(z.x, cs.y, fmaf( z.y, cs.x, ai[k]));
                }
            }
#pragma unroll
            for (int k = 0; k < 8; ++k) {
                int r = rc + k;
                float2 H = Hs[r * T_S + t];
                float Rr = H.x + ar[k];
                float Ri = H.y + ai[k];
                g_R[(b0 + r) * T_S + t] = make_float2(Rr, Ri);
                ssum = fmaf(Rr, Rr, fmaf(Ri, Ri, ssum));
            }
        }
        g_partial[blockIdx.x * T_S + t] = ssum;
    }
}

// ---------------- gate kernel: one block per t ----------------
__global__ void k_gate(const float* __restrict__ S1, const float* __restrict__ S2) {
    const int t = blockIdx.x;
    __shared__ float sm[256];
    float s = g_partial[threadIdx.x * T_S + t] + g_partial[(threadIdx.x + 256) * T_S + t];
    sm[threadIdx.x] = s;
    __syncthreads();
    for (int k = 128; k > 0; k >>= 1) {
        if (threadIdx.x < k) sm[threadIdx.x] += sm[threadIdx.x + k];
        __syncthreads();
    }
    if (threadIdx.x == 0) {
        float rmean = sqrtf(sm[0] / (float)B_TOTAL);
        float x = S1[0] * (rmean - S2[0]);
        g_gate[t] = 1.0f / (1.0f + expf(-x));
    }
}

// ---------------- final kernel: H = R*g ; h = H @ dft ; out = h * max/5 ----------------
__global__ void __launch_bounds__(THREADS) k_final(float* __restrict__ out) {
    float2* Hs = (float2*)smem_raw;            // ROWS * T_S
    float*  gs = (float*)(Hs + ROWS * T_S);    // T_S
    const int tid = threadIdx.x;
    const int b0  = blockIdx.x * ROWS;
    const float s_out = g_scale[1];

    for (int i = tid; i < T_S; i += THREADS) gs[i] = g_gate[i];
    __syncthreads();

    for (int i = tid; i < ROWS * T_S; i += THREADS) {
        int r = i >> 9, t = i & (T_S - 1);
        float2 R = g_R[(b0 + r) * T_S + t];
        float gv = gs[t];
        Hs[i] = make_float2(R.x * gv, R.y * gv);
    }
    __syncthreads();

    const int f  = tid & 63;
    const int rg = tid >> 6;
    if (f < F_S) {
        float hr[ROWS / 4], hi[ROWS / 4];
#pragma unroll
        for (int j = 0; j < ROWS / 4; ++j) { hr[j] = 0.0f; hi[j] = 0.0f; }
#pragma unroll 4
        for (int t = 0; t < T_S; ++t) {
            float2 cs = g_cs_tf[t * F_S + f];
#pragma unroll
            for (int j = 0; j < ROWS / 4; ++j) {
                float2 H = Hs[(rg + 4 * j) * T_S + t];
                hr[j] = fmaf(H.x, cs.x, fmaf(H.y,  cs.y, hr[j]));
                hi[j] = fmaf(H.y, cs.x, fmaf(-H.x, cs.y, hi[j]));
            }
        }
#pragma unroll
        for (int j = 0; j < ROWS / 4; ++j) {
            int r = rg + 4 * j;
            ((float2*)out)[(b0 + r) * F_S + f] = make_float2(hr[j] * s_out, hi[j] * s_out);
        }
    }
}

// ---------------- launch ----------------
extern "C" void kernel_launch(void* const* d_in, const int* in_sizes, int n_in,
                              void* d_out, int out_size) {
    const float* u  = (const float*)d_in[0];
    const float* S1 = (const float*)d_in[1];
    const float* S2 = (const float*)d_in[2];
    float* out = (float*)d_out;

    const int smem_layer = (ROWS * T_S + ROWS * F_S) * (int)sizeof(float2) + T_S * (int)sizeof(float);
    const int smem_final = ROWS * T_S * (int)sizeof(float2) + T_S * (int)sizeof(float);
    cudaFuncSetAttribute(k_layer, cudaFuncAttributeMaxDynamicSharedMemorySize, smem_layer);
    cudaFuncSetAttribute(k_final, cudaFuncAttributeMaxDynamicSharedMemorySize, smem_final);

    const int n = B_TOTAL * F_S * 2;
    k_max1<<<256, 256>>>(u, n);
    k_max2<<<1, 256>>>();
    k_tw<<<(T_S * F_S + 255) / 256, 256>>>();

    for (int l = 0; l < N_LAYERS; ++l) {
        k_layer<<<NCTA, THREADS, smem_layer>>>(u, l == 0 ? 1 : 0);
        k_gate<<<T_S, 256>>>(S1, S2);
    }
    k_final<<<NCTA, THREADS, smem_final>>>(out);

    (void)in_sizes; (void)n_in; (void)out_size;
}

// round 2
// speedup vs baseline: 3.0632x; 3.0632x over previous
#include <cuda_runtime.h>
#include <math.h>

#define B_TOTAL  16384
#define F_S      48
#define T_S      512
#define N_LAYERS 16
#define TILE_R   4
#define NTILES   (B_TOTAL / TILE_R)   // 4096
#define GRID     512
#define THREADS  256
#define GPAD     65                    // 64 + 1 pad (bank-conflict break)

// ---------------- device scratch ----------------
__device__ float2 g_R[B_TOTAL * T_S];          // 64 MB state
__device__ float  g_partial[T_S * NTILES];     // [t][tile] 8 MB
__device__ float  g_gate[T_S];
__device__ float2 c_Phi_f[8 * T_S];            // e^{-2pi i d t/512}
__device__ float2 c_Phi_i[8 * T_S];            // e^{+2pi i d t/512}
__device__ float2 c_T64f[6 * 64];              // e^{-2pi i c t'/64} / sqrt(512)
__device__ float2 c_T64i[6 * 64];              // e^{+2pi i c t'/64} / sqrt(512)
__device__ float  g_scale[2];
__device__ float  g_maxpart[256];
__device__ unsigned g_ticket;
__device__ unsigned g_bar_count;
__device__ volatile unsigned g_bar_gen;

// ---------------- grid barrier ----------------
__device__ __forceinline__ void grid_bar() {
    __syncthreads();
    if (threadIdx.x == 0) {
        unsigned gen = g_bar_gen;
        __threadfence();
        if (atomicAdd(&g_bar_count, 1u) == GRID - 1u) {
            g_bar_count = 0;
            __threadfence();
            g_bar_gen = gen + 1u;
        } else {
            while (g_bar_gen == gen) __nanosleep(128);
        }
    }
    __syncthreads();
}

// ---------------- max reduction ----------------
__global__ void k_max1(const float* __restrict__ u, int n) {
    float m = -INFINITY;
    for (int i = blockIdx.x * blockDim.x + threadIdx.x; i < n; i += gridDim.x * blockDim.x)
        m = fmaxf(m, u[i]);
    __shared__ float sm[256];
    sm[threadIdx.x] = m;
    __syncthreads();
    for (int s = 128; s > 0; s >>= 1) {
        if (threadIdx.x < s) sm[threadIdx.x] = fmaxf(sm[threadIdx.x], sm[threadIdx.x + s]);
        __syncthreads();
    }
    if (threadIdx.x == 0) g_maxpart[blockIdx.x] = sm[0];
}

__global__ void k_max2() {
    __shared__ float sm[256];
    sm[threadIdx.x] = g_maxpart[threadIdx.x];
    __syncthreads();
    for (int s = 128; s > 0; s >>= 1) {
        if (threadIdx.x < s) sm[threadIdx.x] = fmaxf(sm[threadIdx.x], sm[threadIdx.x + s]);
        __syncthreads();
    }
    if (threadIdx.x == 0) {
        float m = fabsf(sm[0]);
        g_scale[0] = 5.0f / m;
        g_scale[1] = m / 5.0f;
    }
}

// ---------------- twiddle tables (exact integer phase) ----------------
__global__ void k_tw() {
    int i = blockIdx.x * blockDim.x + threadIdx.x;
    double sc = 1.0 / sqrt((double)T_S);
    if (i < 8 * T_S) {
        int d = i / T_S, t = i % T_S;
        int k = (d * t) % T_S;
        double ang = 2.0 * M_PI * (double)k / (double)T_S;
        double s, c; sincos(ang, &s, &c);
        c_Phi_f[i] = make_float2((float)c, (float)(-s));
        c_Phi_i[i] = make_float2((float)c, (float)( s));
    }
    if (i < 6 * 64) {
        int c6 = i / 64, tp = i % 64;
        int k = (c6 * tp) % 64;
        double ang = 2.0 * M_PI * (double)k / 64.0;
        double s, c; sincos(ang, &s, &c);
        c_T64f[i] = make_float2((float)(c * sc), (float)(-s * sc));
        c_T64i[i] = make_float2((float)(c * sc), (float)( s * sc));
    }
}

// ---------------- persistent fused network kernel ----------------
__global__ void __launch_bounds__(THREADS, 4)
k_net(const float* __restrict__ u, const float* __restrict__ S1,
      const float* __restrict__ S2, float* __restrict__ out) {
    __shared__ float2 Hs[TILE_R * T_S];        // gated H tile   16 KB
    __shared__ float2 Gs[TILE_R * 8 * GPAD];   // G / S buffer   16.25 KB
    __shared__ float2 zsm[TILE_R * F_S];       // z tile          1.5 KB
    __shared__ float  gsm[T_S];                // gate            2 KB
    __shared__ float  psum[T_S];               // |R|^2 partial   2 KB
    __shared__ float  red[THREADS];
    __shared__ unsigned s_tile;

    const int tid = threadIdx.x;
    const float s_in = g_scale[0];

    if (blockIdx.x == 0 && tid == 0) g_ticket = 0;
    grid_bar();

    for (int layer = 0; layer < N_LAYERS; ++layer) {
        const bool first = (layer == 0);
        if (!first) {
            for (int i = tid; i < T_S; i += THREADS) gsm[i] = __ldcg(&g_gate[i]);
        }
        __syncthreads();

        // -------- tile loop (work stealing) --------
        for (;;) {
            if (tid == 0) s_tile = atomicAdd(&g_ticket, 1u);
            __syncthreads();
            unsigned tile = s_tile;
            if (tile >= NTILES) break;
            const int b0 = (int)tile * TILE_R;

            // stage H = R_prev * g (coherent L2 read)
            if (!first) {
#pragma unroll
                for (int k = 0; k < 8; ++k) {
                    int o = tid + (k << 8);
                    int t = o & (T_S - 1), r = o >> 9;
                    float2 Rv = __ldcg(&g_R[(b0 + r) * T_S + t]);
                    float gv = gsm[t];
                    Hs[o] = make_float2(Rv.x * gv, Rv.y * gv);
                }
            }
            __syncthreads();

            // ---- G stage: G[r][d][t'] = sum_q H[64q+t'] * Phi_f[d][64q+t'] ----
            if (!first) {
#pragma unroll
                for (int k = 0; k < 8; ++k) {
                    int o = tid + (k << 8);
                    int tp = o & 63, rd = o >> 6;
                    int d = rd & 7, r = rd >> 3;
                    const float2* Hr = &Hs[r * T_S];
                    const float2* Ph = &c_Phi_f[d * T_S];
                    float ar = 0.f, ai = 0.f;
#pragma unroll
                    for (int q = 0; q < 8; ++q) {
                        int t = (q << 6) + tp;
                        float2 H = Hr[t];
                        float2 p = Ph[t];
                        ar = fmaf(H.x, p.x, fmaf(-H.y, p.y, ar));
                        ai = fmaf(H.x, p.y, fmaf( H.y, p.x, ai));
                    }
                    Gs[rd * GPAD + tp] = make_float2(ar, ai);
                }
            }
            __syncthreads();

            // ---- h & z: h[8c+d] = sum_t' T64f[c][t'] * G[d][t'] ; z = u*s - h ----
            for (int o = tid; o < TILE_R * F_S; o += THREADS) {
                int f = o % F_S, r = o / F_S;
                int c = f >> 3, d = f & 7;
                float hr = 0.f, hi = 0.f;
                if (!first) {
                    const float2* Grd = &Gs[(r * 8 + d) * GPAD];
                    const float2* Tw = &c_T64f[c * 64];
#pragma unroll 8
                    for (int tp = 0; tp < 64; ++tp) {
                        float2 G = Grd[tp];
                        float2 w = Tw[tp];
                        hr = fmaf(G.x, w.x, fmaf(-G.y, w.y, hr));
                        hi = fmaf(G.x, w.y, fmaf( G.y, w.x, hi));
                    }
                }
                float2 uv = ((const float2*)u)[(b0 + r) * F_S + f];
                zsm[r * F_S + f] = make_float2(uv.x * s_in - hr, uv.y * s_in - hi);
            }
            __syncthreads();

            // ---- S stage: S[r][d][t'] = sum_c z[8c+d] * T64i[c][t'] (overwrites Gs) ----
#pragma unroll
            for (int k = 0; k < 8; ++k) {
                int o = tid + (k << 8);
                int tp = o & 63, rd = o >> 6;
                int d = rd & 7, r = rd >> 3;
                float sr = 0.f, si = 0.f;
#pragma unroll
                for (int c = 0; c < 6; ++c) {
                    float2 z = zsm[r * F_S + (c << 3) + d];
                    float2 w = c_T64i[(c << 6) + tp];
                    sr = fmaf(z.x, w.x, fmaf(-z.y, w.y, sr));
                    si = fmaf(z.x, w.y, fmaf( z.y, w.x, si));
                }
                Gs[rd * GPAD + tp] = make_float2(sr, si);
            }
            __syncthreads();

            // ---- Z/R stage: Z[t] = sum_d S[d][t%64]*Phi_i[d][t]; R = H + Z ----
#pragma unroll
            for (int k = 0; k < 8; ++k) {
                int o = tid + (k << 8);
                int t = o & (T_S - 1), r = o >> 9;
                int tp = t & 63;
                const float2* Sr = &Gs[r * 8 * GPAD];
                float zr = 0.f, zi = 0.f;
#pragma unroll
                for (int d = 0; d < 8; ++d) {
                    float2 S = Sr[d * GPAD + tp];
                    float2 w = c_Phi_i[d * T_S + t];
                    zr = fmaf(S.x, w.x, fmaf(-S.y, w.y, zr));
                    zi = fmaf(S.x, w.y, fmaf( S.y, w.x, zi));
                }
                float Rr, Ri;
                if (first) { Rr = zr; Ri = zi; }
                else {
                    float2 H = Hs[o];
                    Rr = H.x + zr; Ri = H.y + zi;
                }
                g_R[(b0 + r) * T_S + t] = make_float2(Rr, Ri);
                float v = fmaf(Rr, Rr, Ri * Ri);
                if (o < T_S) psum[t] = v; else psum[t] += v;  // owner: t % 256 == tid
            }
            __syncthreads();
            for (int t = tid; t < T_S; t += THREADS)
                g_partial[t * NTILES + tile] = psum[t];
        }
        grid_bar();

        // -------- gate stage: CTA b handles t = b --------
        {
            int t = blockIdx.x;
            float s = 0.f;
#pragma unroll
            for (int j = 0; j < NTILES / THREADS; ++j)
                s += __ldcg(&g_partial[t * NTILES + tid + j * THREADS]);
            red[tid] = s;
            __syncthreads();
            for (int k = 128; k > 0; k >>= 1) {
                if (tid < k) red[tid] += red[tid + k];
                __syncthreads();
            }
            if (tid == 0) {
                float rmean = sqrtf(red[0] * (1.0f / (float)B_TOTAL));
                float x = S1[0] * (rmean - S2[0]);
                g_gate[t] = 1.0f / (1.0f + expf(-x));
                if (t == 0) g_ticket = 0;
            }
        }
        grid_bar();
    }

    // -------- final: out = dft(R * g) * s_out --------
    for (int i = tid; i < T_S; i += THREADS) gsm[i] = __ldcg(&g_gate[i]);
    __syncthreads();
    const float s_out = g_scale[1];
    for (;;) {
        if (tid == 0) s_tile = atomicAdd(&g_ticket, 1u);
        __syncthreads();
        unsigned tile = s_tile;
        if (tile >= NTILES) break;
        const int b0 = (int)tile * TILE_R;

#pragma unroll
        for (int k = 0; k < 8; ++k) {
            int o = tid + (k << 8);
            int t = o & (T_S - 1), r = o >> 9;
            float2 Rv = __ldcg(&g_R[(b0 + r) * T_S + t]);
            float gv = gsm[t];
            Hs[o] = make_float2(Rv.x * gv, Rv.y * gv);
        }
        __syncthreads();
#pragma unroll
        for (int k = 0; k < 8; ++k) {
            int o = tid + (k << 8);
            int tp = o & 63, rd = o >> 6;
            int d = rd & 7, r = rd >> 3;
            const float2* Hr = &Hs[r * T_S];
            const float2* Ph = &c_Phi_f[d * T_S];
            float ar = 0.f, ai = 0.f;
#pragma unroll
            for (int q = 0; q < 8; ++q) {
                int t = (q << 6) + tp;
                float2 H = Hr[t];
                float2 p = Ph[t];
                ar = fmaf(H.x, p.x, fmaf(-H.y, p.y, ar));
                ai = fmaf(H.x, p.y, fmaf( H.y, p.x, ai));
            }
            Gs[rd * GPAD + tp] = make_float2(ar, ai);
        }
        __syncthreads();
        for (int o = tid; o < TILE_R * F_S; o += THREADS) {
            int f = o % F_S, r = o / F_S;
            int c = f >> 3, d = f & 7;
            const float2* Grd = &Gs[(r * 8 + d) * GPAD];
            const float2* Tw = &c_T64f[c * 64];
            float hr = 0.f, hi = 0.f;
#pragma unroll 8
            for (int tp = 0; tp < 64; ++tp) {
                float2 G = Grd[tp];
                float2 w = Tw[tp];
                hr = fmaf(G.x, w.x, fmaf(-G.y, w.y, hr));
                hi = fmaf(G.x, w.y, fmaf( G.y, w.x, hi));
            }
            ((float2*)out)[(b0 + r) * F_S + f] = make_float2(hr * s_out, hi * s_out);
        }
        __syncthreads();
    }
}

// ---------------- launch ----------------
extern "C" void kernel_launch(void* const* d_in, const int* in_sizes, int n_in,
                              void* d_out, int out_size) {
    const float* u  = (const float*)d_in[0];
    const float* S1 = (const float*)d_in[1];
    const float* S2 = (const float*)d_in[2];
    float* out = (float*)d_out;

    const int n = B_TOTAL * F_S * 2;
    k_max1<<<256, 256>>>(u, n);
    k_max2<<<1, 256>>>();
    k_tw<<<(8 * T_S + 255) / 256, 256>>>();
    k_net<<<GRID, THREADS>>>(u, S1, S2, out);

    (void)in_sizes; (void)n_in; (void)out_size;
}

// round 3
// speedup vs baseline: 6.6246x; 2.1627x over previous
#include <cuda_runtime.h>
#include <math.h>

#define B_TOTAL  16384
#define F_S      48
#define T_S      512
#define N_LAYERS 16
#define TILE_R   8
#define NTILES   (B_TOTAL / TILE_R)   // 2048
#define GRID     296
#define THREADS  256
#define GPAD     66                   // float2 stride pad for [r][d][tp]

// ---------------- device scratch ----------------
__device__ float2 g_R[B_TOTAL * T_S];          // 64 MB state
__device__ float  g_partial[T_S * NTILES];     // [t][tile] 4 MB
__device__ float  g_gate[T_S];
__device__ float2 c_w64[64];                   // e^{-2pi i tp/512}, tp in [0,64)
__device__ float2 c_cb[48];                    // e^{-2pi i c b/64} / sqrt(512)
__device__ float  g_scale[2];
__device__ float  g_maxpart[256];
__device__ unsigned g_ticket;
__device__ unsigned g_bar_count;
__device__ volatile unsigned g_bar_gen;

// ---------------- complex helpers ----------------
__device__ __forceinline__ float2 cadd(float2 a, float2 b) { return make_float2(a.x + b.x, a.y + b.y); }
__device__ __forceinline__ float2 csub(float2 a, float2 b) { return make_float2(a.x - b.x, a.y - b.y); }
__device__ __forceinline__ float2 cmul(float2 a, float2 b) {
    return make_float2(fmaf(a.x, b.x, -a.y * b.y), fmaf(a.x, b.y, a.y * b.x));
}
__device__ __forceinline__ float2 cmulj(float2 a, float2 b) {   // a * conj(b)
    return make_float2(fmaf(a.x, b.x, a.y * b.y), fmaf(a.y, b.x, -a.x * b.y));
}

#define SQ2H 0.70710678118654752f

// X[k] = sum_n h[n] e^{-2pi i nk/8}
__device__ __forceinline__ void fft8f(const float2* h, float2* X) {
    float2 ea0 = cadd(h[0], h[4]), ea1 = csub(h[0], h[4]);
    float2 eb0 = cadd(h[2], h[6]), eb1 = csub(h[2], h[6]);
    float2 oa0 = cadd(h[1], h[5]), oa1 = csub(h[1], h[5]);
    float2 ob0 = cadd(h[3], h[7]), ob1 = csub(h[3], h[7]);
    float2 E0 = cadd(ea0, eb0), E2 = csub(ea0, eb0);
    float2 mieb = make_float2(eb1.y, -eb1.x);                  // -i*eb1
    float2 E1 = cadd(ea1, mieb), E3 = csub(ea1, mieb);
    float2 O0 = cadd(oa0, ob0), O2 = csub(oa0, ob0);
    float2 miob = make_float2(ob1.y, -ob1.x);
    float2 O1 = cadd(oa1, miob), O3 = csub(oa1, miob);
    X[0] = cadd(E0, O0); X[4] = csub(E0, O0);
    float2 w1o = make_float2(SQ2H * (O1.x + O1.y), SQ2H * (O1.y - O1.x));   // s(1-i)*O1
    X[1] = cadd(E1, w1o); X[5] = csub(E1, w1o);
    float2 w2o = make_float2(O2.y, -O2.x);                                  // -i*O2
    X[2] = cadd(E2, w2o); X[6] = csub(E2, w2o);
    float2 w3o = make_float2(SQ2H * (O3.y - O3.x), -SQ2H * (O3.x + O3.y));  // -s(1+i)*O3
    X[3] = cadd(E3, w3o); X[7] = csub(E3, w3o);
}

// X[k] = sum_n h[n] e^{+2pi i nk/8}
__device__ __forceinline__ void fft8i(const float2* h, float2* X) {
    float2 ea0 = cadd(h[0], h[4]), ea1 = csub(h[0], h[4]);
    float2 eb0 = cadd(h[2], h[6]), eb1 = csub(h[2], h[6]);
    float2 oa0 = cadd(h[1], h[5]), oa1 = csub(h[1], h[5]);
    float2 ob0 = cadd(h[3], h[7]), ob1 = csub(h[3], h[7]);
    float2 E0 = cadd(ea0, eb0), E2 = csub(ea0, eb0);
    float2 pieb = make_float2(-eb1.y, eb1.x);                  // +i*eb1
    float2 E1 = cadd(ea1, pieb), E3 = csub(ea1, pieb);
    float2 O0 = cadd(oa0, ob0), O2 = csub(oa0, ob0);
    float2 piob = make_float2(-ob1.y, ob1.x);
    float2 O1 = cadd(oa1, piob), O3 = csub(oa1, piob);
    X[0] = cadd(E0, O0); X[4] = csub(E0, O0);
    float2 w1o = make_float2(SQ2H * (O1.x - O1.y), SQ2H * (O1.x + O1.y));   // s(1+i)*O1
    X[1] = cadd(E1, w1o); X[5] = csub(E1, w1o);
    float2 w2o = make_float2(-O2.y, O2.x);                                  // +i*O2
    X[2] = cadd(E2, w2o); X[6] = csub(E2, w2o);
    float2 w3o = make_float2(-SQ2H * (O3.x + O3.y), SQ2H * (O3.x - O3.y));  // s(-1+i)*O3
    X[3] = cadd(E3, w3o); X[7] = csub(E3, w3o);
}

// ---------------- grid barrier ----------------
__device__ __forceinline__ void grid_bar() {
    __syncthreads();
    if (threadIdx.x == 0) {
        unsigned gen = g_bar_gen;
        __threadfence();
        if (atomicAdd(&g_bar_count, 1u) == GRID - 1u) {
            g_bar_count = 0;
            __threadfence();
            g_bar_gen = gen + 1u;
        } else {
            while (g_bar_gen == gen) __nanosleep(64);
        }
        __threadfence();
    }
    __syncthreads();
}

// ---------------- max reduction ----------------
__global__ void k_max1(const float* __restrict__ u, int n) {
    float m = -INFINITY;
    for (int i = blockIdx.x * blockDim.x + threadIdx.x; i < n; i += gridDim.x * blockDim.x)
        m = fmaxf(m, u[i]);
    __shared__ float sm[256];
    sm[threadIdx.x] = m;
    __syncthreads();
    for (int s = 128; s > 0; s >>= 1) {
        if (threadIdx.x < s) sm[threadIdx.x] = fmaxf(sm[threadIdx.x], sm[threadIdx.x + s]);
        __syncthreads();
    }
    if (threadIdx.x == 0) g_maxpart[blockIdx.x] = sm[0];
}

__global__ void k_max2() {
    __shared__ float sm[256];
    sm[threadIdx.x] = g_maxpart[threadIdx.x];
    __syncthreads();
    for (int s = 128; s > 0; s >>= 1) {
        if (threadIdx.x < s) sm[threadIdx.x] = fmaxf(sm[threadIdx.x], sm[threadIdx.x + s]);
        __syncthreads();
    }
    if (threadIdx.x == 0) {
        float m = fabsf(sm[0]);
        g_scale[0] = 5.0f / m;
        g_scale[1] = m / 5.0f;
    }
}

// ---------------- tables ----------------
__global__ void k_tw() {
    int i = threadIdx.x;
    if (i < 64) {
        double ang = 2.0 * M_PI * (double)i / 512.0;
        double s, c; sincos(ang, &s, &c);
        c_w64[i] = make_float2((float)c, (float)(-s));     // e^{-2pi i tp/512}
    }
    if (i < 48) {
        int cc = i >> 3, b = i & 7;
        double sc = 1.0 / sqrt(512.0);
        double ang = 2.0 * M_PI * (double)(cc * b) / 64.0;
        double s, c; sincos(ang, &s, &c);
        c_cb[i] = make_float2((float)(c * sc), (float)(-s * sc));  // e^{-2pi i cb/64}/sqrt(512)
    }
}

// ---------------- persistent fused network kernel ----------------
extern __shared__ float smem_raw[];

__global__ void __launch_bounds__(THREADS, 2)
k_net(const float* __restrict__ u, const float* __restrict__ S1,
      const float* __restrict__ S2, float* __restrict__ out) {
    float2* Hs  = (float2*)smem_raw;                 // [8][512]      32 KB
    float2* Gs  = Hs + TILE_R * T_S;                 // [8][8][GPAD]  33.8 KB
    float2* zsm = Gs + TILE_R * 8 * GPAD;            // [8][48]        3 KB
    float*  gsm = (float*)(zsm + TILE_R * F_S);      // [512]          2 KB
    float*  ps2 = gsm + T_S;                         // [4][512]       8 KB
    float*  red = ps2 + 4 * T_S;                     // [256]          1 KB
    unsigned* s_tile = (unsigned*)(red + THREADS);

    const int tid = threadIdx.x;
    const float s_in = g_scale[0];

    if (blockIdx.x == 0 && tid == 0) g_ticket = 0;
    grid_bar();

    for (int layer = 0; layer <= N_LAYERS; ++layer) {
        const bool first = (layer == 0);
        const bool last  = (layer == N_LAYERS);      // final projection pass
        if (!first) {
            for (int i = tid; i < T_S; i += THREADS) gsm[i] = __ldcg(&g_gate[i]);
        }
        __syncthreads();

        for (;;) {
            if (tid == 0) *s_tile = atomicAdd(&g_ticket, 1u);
            __syncthreads();
            unsigned tile = *s_tile;
            if (tile >= NTILES) break;
            const int b0 = (int)tile * TILE_R;

            // ---- stage H: Hs = R_prev * g ----
            if (!first) {
#pragma unroll
                for (int k = 0; k < 16; ++k) {
                    int o = tid + (k << 8);
                    int t = o & (T_S - 1), r = o >> 9;
                    float2 Rv = __ldcg(&g_R[(b0 + r) * T_S + t]);
                    float gv = gsm[t];
                    Hs[o] = make_float2(Rv.x * gv, Rv.y * gv);
                }
            }
            __syncthreads();

            // ---- stage G: G[r][d][tp] = w^d * fft8_q(H[r][64q+tp]) ----
            if (!first) {
#pragma unroll
                for (int pass = 0; pass < 2; ++pass) {
                    int o = tid + (pass << 8);
                    int tp = o & 63, r = o >> 6;
                    float2 hh[8], X[8];
#pragma unroll
                    for (int q = 0; q < 8; ++q) hh[q] = Hs[r * T_S + (q << 6) + tp];
                    fft8f(hh, X);
                    float2 w = c_w64[tp];
                    float2 cw = make_float2(1.0f, 0.0f);
#pragma unroll
                    for (int d = 0; d < 8; ++d) {
                        Gs[(r * 8 + d) * GPAD + tp] = cmul(X[d], cw);
                        cw = cmul(cw, w);
                    }
                }
            }
            __syncthreads();

            // ---- stage A/h: h[8c+d] = sum_b c_cb[c][b] * fft8_a(G[d][8a+b])[c]; z = u*s - h ----
            if (first) {
                for (int o = tid; o < TILE_R * F_S; o += THREADS) {
                    int r = o / F_S, f = o - r * F_S;
                    float2 uv = ((const float2*)u)[(b0 + r) * F_S + f];
                    zsm[o] = make_float2(uv.x * s_in, uv.y * s_in);
                }
            } else {
#pragma unroll
                for (int pass = 0; pass < 2; ++pass) {
                    int o = tid + (pass << 8);
                    int b = o & 7, d = (o >> 3) & 7, r = o >> 6;
                    float2 Gv[8], A[8];
#pragma unroll
                    for (int a = 0; a < 8; ++a) Gv[a] = Gs[(r * 8 + d) * GPAD + (a << 3) + b];
                    fft8f(Gv, A);
                    float2 p[6];
#pragma unroll
                    for (int c = 0; c < 6; ++c) p[c] = cmul(A[c], c_cb[c * 8 + b]);
#pragma unroll
                    for (int m = 1; m < 8; m <<= 1) {
#pragma unroll
                        for (int c = 0; c < 6; ++c) {
                            p[c].x += __shfl_xor_sync(0xFFFFFFFFu, p[c].x, m);
                            p[c].y += __shfl_xor_sync(0xFFFFFFFFu, p[c].y, m);
                        }
                    }
                    if (b == 0) {
                        if (last) {
                            const float s_out = g_scale[1];
#pragma unroll
                            for (int c = 0; c < 6; ++c)
                                ((float2*)out)[(b0 + r) * F_S + (c << 3) + d] =
                                    make_float2(p[c].x * s_out, p[c].y * s_out);
                        } else {
#pragma unroll
                            for (int c = 0; c < 6; ++c) {
                                float2 uv = ((const float2*)u)[(b0 + r) * F_S + (c << 3) + d];
                                zsm[r * F_S + (c << 3) + d] =
                                    make_float2(uv.x * s_in - p[c].x, uv.y * s_in - p[c].y);
                            }
                        }
                    }
                }
            }
            if (last) { __syncthreads(); continue; }   // final pass: output written, done
            __syncthreads();

            // ---- stage S: S[r][d][8a+b] = ifft8_c( z[8c+d] * conj(c_cb[c][b]) )[a] ----
#pragma unroll
            for (int pass = 0; pass < 2; ++pass) {
                int o = tid + (pass << 8);
                int b = o & 7, d = (o >> 3) & 7, r = o >> 6;
                float2 v[8], S[8];
#pragma unroll
                for (int c = 0; c < 6; ++c)
                    v[c] = cmulj(zsm[r * F_S + (c << 3) + d], c_cb[c * 8 + b]);
                v[6] = make_float2(0.f, 0.f);
                v[7] = make_float2(0.f, 0.f);
                fft8i(v, S);
#pragma unroll
                for (int a = 0; a < 8; ++a)
                    Gs[(r * 8 + d) * GPAD + (a << 3) + b] = S[a];
            }
            __syncthreads();

            // ---- stage Z/R: Z[64q+tp] = ifft8_d( S[d][tp] * conj(w)^d )[q]; R = H + Z ----
            {
                float acc[8];
#pragma unroll
                for (int q = 0; q < 8; ++q) acc[q] = 0.f;
                int tp = tid & 63;
#pragma unroll
                for (int pass = 0; pass < 2; ++pass) {
                    int o = tid + (pass << 8);
                    int r = o >> 6;
                    float2 w = c_w64[tp];
                    w.y = -w.y;                       // e^{+2pi i tp/512}
                    float2 v[8], Z[8];
                    float2 cw = make_float2(1.0f, 0.0f);
#pragma unroll
                    for (int d = 0; d < 8; ++d) {
                        v[d] = cmul(Gs[(r * 8 + d) * GPAD + tp], cw);
                        cw = cmul(cw, w);
                    }
                    fft8i(v, Z);
#pragma unroll
                    for (int q = 0; q < 8; ++q) {
                        int t = (q << 6) + tp;
                        float Rr = Z[q].x, Ri = Z[q].y;
                        if (!first) {
                            float2 H = Hs[r * T_S + t];
                            Rr += H.x; Ri += H.y;
                        }
                        g_R[(b0 + r) * T_S + t] = make_float2(Rr, Ri);
                        acc[q] = fmaf(Rr, Rr, fmaf(Ri, Ri, acc[q]));
                    }
                }
                int rg = tid >> 6;
#pragma unroll
                for (int q = 0; q < 8; ++q) ps2[rg * T_S + (q << 6) + tp] = acc[q];
            }
            __syncthreads();
            for (int t = tid; t < T_S; t += THREADS) {
                float s = ps2[t] + ps2[T_S + t] + ps2[2 * T_S + t] + ps2[3 * T_S + t];
                g_partial[t * NTILES + tile] = s;
            }
        }
        if (last) break;
        grid_bar();

        // -------- gate stage --------
        for (int t = blockIdx.x; t < T_S; t += GRID) {
            float s = 0.f;
#pragma unroll
            for (int j = 0; j < NTILES / THREADS; ++j)
                s += __ldcg(&g_partial[t * NTILES + tid + j * THREADS]);
            red[tid] = s;
            __syncthreads();
            for (int k = 128; k > 0; k >>= 1) {
                if (tid < k) red[tid] += red[tid + k];
                __syncthreads();
            }
            if (tid == 0) {
                float rmean = sqrtf(red[0] * (1.0f / (float)B_TOTAL));
                float x = S1[0] * (rmean - S2[0]);
                g_gate[t] = 1.0f / (1.0f + expf(-x));
                if (t == 0) g_ticket = 0;
            }
            __syncthreads();
        }
        grid_bar();
    }
}

// ---------------- launch ----------------
extern "C" void kernel_launch(void* const* d_in, const int* in_sizes, int n_in,
                              void* d_out, int out_size) {
    const float* u  = (const float*)d_in[0];
    const float* S1 = (const float*)d_in[1];
    const float* S2 = (const float*)d_in[2];
    float* out = (float*)d_out;

    const int smem = (TILE_R * T_S + TILE_R * 8 * GPAD + TILE_R * F_S) * (int)sizeof(float2)
                   + (T_S + 4 * T_S + THREADS + 8) * (int)sizeof(float);
    cudaFuncSetAttribute(k_net, cudaFuncAttributeMaxDynamicSharedMemorySize, smem);

    const int n = B_TOTAL * F_S * 2;
    k_max1<<<256, 256>>>(u, n);
    k_max2<<<1, 256>>>();
    k_tw<<<1, 64>>>();
    k_net<<<GRID, THREADS, smem>>>(u, S1, S2, out);

    (void)in_sizes; (void)n_in; (void)out_size;
}

// round 4
// speedup vs baseline: 6.7108x; 1.0130x over previous
#include <cuda_runtime.h>
#include <math.h>

#define B_TOTAL  16384
#define F_S      48
#define T_S      512
#define N_LAYERS 16
#define TILE_R   4
#define NTILES   (B_TOTAL / TILE_R)   // 4096
#define GRID     444                  // 3 CTAs x 148 SMs, all resident
#define THREADS  256
#define GPAD     72                   // float2 stride: (2*GPAD)%64==16 -> conflict-free A/S stages

// ---------------- device scratch ----------------
__device__ float2 g_R[B_TOTAL * T_S];          // 64 MB state (L2-resident)
__device__ float  g_partial[T_S * NTILES];     // [t][tile] 8 MB
__device__ float  g_gate[T_S];
__device__ float2 c_w64[64];                   // e^{-2pi i tp/512}
__device__ float2 c_cb[48];                    // e^{-2pi i c b/64} / sqrt(512)
__device__ float  g_scale[2];
__device__ float  g_maxpart[256];
__device__ unsigned g_ticket;
__device__ unsigned g_bar_count;
__device__ volatile unsigned g_bar_gen;

// ---------------- complex helpers ----------------
__device__ __forceinline__ float2 cadd(float2 a, float2 b) { return make_float2(a.x + b.x, a.y + b.y); }
__device__ __forceinline__ float2 csub(float2 a, float2 b) { return make_float2(a.x - b.x, a.y - b.y); }
__device__ __forceinline__ float2 cmul(float2 a, float2 b) {
    return make_float2(fmaf(a.x, b.x, -a.y * b.y), fmaf(a.x, b.y, a.y * b.x));
}
__device__ __forceinline__ float2 cmulj(float2 a, float2 b) {   // a * conj(b)
    return make_float2(fmaf(a.x, b.x, a.y * b.y), fmaf(a.y, b.x, -a.x * b.y));
}

#define SQ2H 0.70710678118654752f

// X[k] = sum_n h[n] e^{-2pi i nk/8}
__device__ __forceinline__ void fft8f(const float2* h, float2* X) {
    float2 ea0 = cadd(h[0], h[4]), ea1 = csub(h[0], h[4]);
    float2 eb0 = cadd(h[2], h[6]), eb1 = csub(h[2], h[6]);
    float2 oa0 = cadd(h[1], h[5]), oa1 = csub(h[1], h[5]);
    float2 ob0 = cadd(h[3], h[7]), ob1 = csub(h[3], h[7]);
    float2 E0 = cadd(ea0, eb0), E2 = csub(ea0, eb0);
    float2 mieb = make_float2(eb1.y, -eb1.x);
    float2 E1 = cadd(ea1, mieb), E3 = csub(ea1, mieb);
    float2 O0 = cadd(oa0, ob0), O2 = csub(oa0, ob0);
    float2 miob = make_float2(ob1.y, -ob1.x);
    float2 O1 = cadd(oa1, miob), O3 = csub(oa1, miob);
    X[0] = cadd(E0, O0); X[4] = csub(E0, O0);
    float2 w1o = make_float2(SQ2H * (O1.x + O1.y), SQ2H * (O1.y - O1.x));
    X[1] = cadd(E1, w1o); X[5] = csub(E1, w1o);
    float2 w2o = make_float2(O2.y, -O2.x);
    X[2] = cadd(E2, w2o); X[6] = csub(E2, w2o);
    float2 w3o = make_float2(SQ2H * (O3.y - O3.x), -SQ2H * (O3.x + O3.y));
    X[3] = cadd(E3, w3o); X[7] = csub(E3, w3o);
}

// X[k] = sum_n h[n] e^{+2pi i nk/8}
__device__ __forceinline__ void fft8i(const float2* h, float2* X) {
    float2 ea0 = cadd(h[0], h[4]), ea1 = csub(h[0], h[4]);
    float2 eb0 = cadd(h[2], h[6]), eb1 = csub(h[2], h[6]);
    float2 oa0 = cadd(h[1], h[5]), oa1 = csub(h[1], h[5]);
    float2 ob0 = cadd(h[3], h[7]), ob1 = csub(h[3], h[7]);
    float2 E0 = cadd(ea0, eb0), E2 = csub(ea0, eb0);
    float2 pieb = make_float2(-eb1.y, eb1.x);
    float2 E1 = cadd(ea1, pieb), E3 = csub(ea1, pieb);
    float2 O0 = cadd(oa0, ob0), O2 = csub(oa0, ob0);
    float2 piob = make_float2(-ob1.y, ob1.x);
    float2 O1 = cadd(oa1, piob), O3 = csub(oa1, piob);
    X[0] = cadd(E0, O0); X[4] = csub(E0, O0);
    float2 w1o = make_float2(SQ2H * (O1.x - O1.y), SQ2H * (O1.x + O1.y));
    X[1] = cadd(E1, w1o); X[5] = csub(E1, w1o);
    float2 w2o = make_float2(-O2.y, O2.x);
    X[2] = cadd(E2, w2o); X[6] = csub(E2, w2o);
    float2 w3o = make_float2(-SQ2H * (O3.x + O3.y), SQ2H * (O3.x - O3.y));
    X[3] = cadd(E3, w3o); X[7] = csub(E3, w3o);
}

// ---------------- grid barrier ----------------
__device__ __forceinline__ void grid_bar() {
    __syncthreads();
    if (threadIdx.x == 0) {
        unsigned gen = g_bar_gen;
        __threadfence();
        if (atomicAdd(&g_bar_count, 1u) == GRID - 1u) {
            g_bar_count = 0;
            __threadfence();
            g_bar_gen = gen + 1u;
        } else {
            while (g_bar_gen == gen) __nanosleep(64);
        }
        __threadfence();
    }
    __syncthreads();
}

// ---------------- max reduction ----------------
__global__ void k_max1(const float* __restrict__ u, int n) {
    float m = -INFINITY;
    for (int i = blockIdx.x * blockDim.x + threadIdx.x; i < n; i += gridDim.x * blockDim.x)
        m = fmaxf(m, u[i]);
    __shared__ float sm[256];
    sm[threadIdx.x] = m;
    __syncthreads();
    for (int s = 128; s > 0; s >>= 1) {
        if (threadIdx.x < s) sm[threadIdx.x] = fmaxf(sm[threadIdx.x], sm[threadIdx.x + s]);
        __syncthreads();
    }
    if (threadIdx.x == 0) g_maxpart[blockIdx.x] = sm[0];
}

__global__ void k_max2() {
    __shared__ float sm[256];
    sm[threadIdx.x] = g_maxpart[threadIdx.x];
    __syncthreads();
    for (int s = 128; s > 0; s >>= 1) {
        if (threadIdx.x < s) sm[threadIdx.x] = fmaxf(sm[threadIdx.x], sm[threadIdx.x + s]);
        __syncthreads();
    }
    if (threadIdx.x == 0) {
        float m = fabsf(sm[0]);
        g_scale[0] = 5.0f / m;
        g_scale[1] = m / 5.0f;
    }
}

// ---------------- tables ----------------
__global__ void k_tw() {
    int i = threadIdx.x;
    if (i < 64) {
        double ang = 2.0 * M_PI * (double)i / 512.0;
        double s, c; sincos(ang, &s, &c);
        c_w64[i] = make_float2((float)c, (float)(-s));
    }
    if (i < 48) {
        int cc = i >> 3, b = i & 7;
        double sc = 1.0 / sqrt(512.0);
        double ang = 2.0 * M_PI * (double)(cc * b) / 64.0;
        double s, c; sincos(ang, &s, &c);
        c_cb[i] = make_float2((float)(c * sc), (float)(-s * sc));
    }
}

// ---------------- persistent fused network kernel ----------------
extern __shared__ float smem_raw[];

__global__ void __launch_bounds__(THREADS, 3)
k_net(const float* __restrict__ u, const float* __restrict__ S1,
      const float* __restrict__ S2, float* __restrict__ out) {
    float2* Gs  = (float2*)smem_raw;                 // [4*8][GPAD]  18.4 KB
    float2* zsm = Gs + TILE_R * 8 * GPAD;            // [4][48]       1.5 KB
    float*  gsm = (float*)(zsm + TILE_R * F_S);      // [512]         2 KB
    float*  ps2 = gsm + T_S;                         // [4][512]      8 KB
    float*  red = ps2 + 4 * T_S;                     // [256]         1 KB
    unsigned* s_tile = (unsigned*)(red + THREADS);

    const int tid = threadIdx.x;
    const float s_in = g_scale[0];
    const int r  = tid >> 6;          // Z/G-stage row
    const int tp = tid & 63;          // Z/G-stage time-within-64
    const int b  = tid & 7;           // A/S-stage radix lane
    const int d  = (tid >> 3) & 7;    // A/S-stage digit

    if (blockIdx.x == 0 && tid == 0) g_ticket = 0;
    grid_bar();

    for (int layer = 0; layer <= N_LAYERS; ++layer) {
        const bool first = (layer == 0);
        const bool last  = (layer == N_LAYERS);
        if (!first) {
            for (int i = tid; i < T_S; i += THREADS) gsm[i] = __ldcg(&g_gate[i]);
        }
        __syncthreads();

        for (;;) {
            if (tid == 0) *s_tile = atomicAdd(&g_ticket, 1u);
            __syncthreads();
            unsigned tile = *s_tile;
            if (tile >= NTILES) break;
            const int b0 = (int)tile * TILE_R;

            // ---- stage G: registers only; G[r][d][tp] = w^d * fft8_q( R*g ) ----
            if (!first) {
                float2 hh[8], X[8];
#pragma unroll
                for (int q = 0; q < 8; ++q) {
                    int t = (q << 6) + tp;
                    float2 Rv = __ldcg(&g_R[(b0 + r) * T_S + t]);
                    float gv = gsm[t];
                    hh[q] = make_float2(Rv.x * gv, Rv.y * gv);
                }
                fft8f(hh, X);
                float2 w = c_w64[tp];
                float2 cw = make_float2(1.0f, 0.0f);
#pragma unroll
                for (int dd = 0; dd < 8; ++dd) {
                    Gs[(r * 8 + dd) * GPAD + tp] = cmul(X[dd], cw);
                    cw = cmul(cw, w);
                }
            }
            __syncthreads();

            // ---- stage A: h[8c+d] = sum_b c_cb[c][b]*fft8_a(G[d][8a+b])[c]; z = u*s - h ----
            if (first) {
                if (tid < TILE_R * F_S) {
                    int rr = tid / F_S, f = tid - rr * F_S;
                    float2 uv = ((const float2*)u)[(b0 + rr) * F_S + f];
                    zsm[tid] = make_float2(uv.x * s_in, uv.y * s_in);
                }
            } else {
                float2 Gv[8], A[8];
#pragma unroll
                for (int a = 0; a < 8; ++a) Gv[a] = Gs[(r * 8 + d) * GPAD + (a << 3) + b];
                fft8f(Gv, A);
                float2 p[6];
#pragma unroll
                for (int c = 0; c < 6; ++c) p[c] = cmul(A[c], c_cb[c * 8 + b]);
#pragma unroll
                for (int m = 1; m < 8; m <<= 1) {
#pragma unroll
                    for (int c = 0; c < 6; ++c) {
                        p[c].x += __shfl_xor_sync(0xFFFFFFFFu, p[c].x, m);
                        p[c].y += __shfl_xor_sync(0xFFFFFFFFu, p[c].y, m);
                    }
                }
                if (b == 0) {
                    if (last) {
                        const float s_out = g_scale[1];
#pragma unroll
                        for (int c = 0; c < 6; ++c)
                            ((float2*)out)[(b0 + r) * F_S + (c << 3) + d] =
                                make_float2(p[c].x * s_out, p[c].y * s_out);
                    } else {
#pragma unroll
                        for (int c = 0; c < 6; ++c) {
                            float2 uv = ((const float2*)u)[(b0 + r) * F_S + (c << 3) + d];
                            zsm[r * F_S + (c << 3) + d] =
                                make_float2(uv.x * s_in - p[c].x, uv.y * s_in - p[c].y);
                        }
                    }
                }
            }
            if (last) { __syncthreads(); continue; }
            __syncthreads();

            // ---- stage S: S[r][d][8a+b] = ifft8_c( z[8c+d]*conj(c_cb[c][b]) )[a] ----
            {
                float2 v[8], S[8];
#pragma unroll
                for (int c = 0; c < 6; ++c)
                    v[c] = cmulj(zsm[r * F_S + (c << 3) + d], c_cb[c * 8 + b]);
                v[6] = make_float2(0.f, 0.f);
                v[7] = make_float2(0.f, 0.f);
                fft8i(v, S);
#pragma unroll
                for (int a = 0; a < 8; ++a)
                    Gs[(r * 8 + d) * GPAD + (a << 3) + b] = S[a];
            }
            __syncthreads();

            // ---- stage Z/R: Z[64q+tp] = ifft8_d( S[d][tp]*conj(w)^d )[q]; R = R_prev*g + Z ----
            {
                float2 w = c_w64[tp];
                w.y = -w.y;
                float2 v[8], Z[8];
                float2 cw = make_float2(1.0f, 0.0f);
#pragma unroll
                for (int dd = 0; dd < 8; ++dd) {
                    v[dd] = cmul(Gs[(r * 8 + dd) * GPAD + tp], cw);
                    cw = cmul(cw, w);
                }
                fft8i(v, Z);
#pragma unroll
                for (int q = 0; q < 8; ++q) {
                    int t = (q << 6) + tp;
                    float Rr = Z[q].x, Ri = Z[q].y;
                    if (!first) {
                        float2 Rv = __ldcg(&g_R[(b0 + r) * T_S + t]);   // L2 hit (read in stage G)
                        float gv = gsm[t];
                        Rr = fmaf(Rv.x, gv, Rr);
                        Ri = fmaf(Rv.y, gv, Ri);
                    }
                    g_R[(b0 + r) * T_S + t] = make_float2(Rr, Ri);
                    ps2[r * T_S + t] = fmaf(Rr, Rr, Ri * Ri);
                }
            }
            __syncthreads();
            for (int t = tid; t < T_S; t += THREADS)
                g_partial[t * NTILES + tile] =
                    ps2[t] + ps2[T_S + t] + ps2[2 * T_S + t] + ps2[3 * T_S + t];
        }
        if (last) break;
        grid_bar();

        // -------- gate stage --------
        for (int t = blockIdx.x; t < T_S; t += GRID) {
            float s = 0.f;
#pragma unroll
            for (int j = 0; j < NTILES / THREADS; ++j)
                s += __ldcg(&g_partial[t * NTILES + tid + j * THREADS]);
            red[tid] = s;
            __syncthreads();
            for (int k = 128; k > 0; k >>= 1) {
                if (tid < k) red[tid] += red[tid + k];
                __syncthreads();
            }
            if (tid == 0) {
                float rmean = sqrtf(red[0] * (1.0f / (float)B_TOTAL));
                float x = S1[0] * (rmean - S2[0]);
                g_gate[t] = 1.0f / (1.0f + expf(-x));
                if (t == 0) g_ticket = 0;
            }
            __syncthreads();
        }
        grid_bar();
    }
}

// ---------------- launch ----------------
extern "C" void kernel_launch(void* const* d_in, const int* in_sizes, int n_in,
                              void* d_out, int out_size) {
    const float* u  = (const float*)d_in[0];
    const float* S1 = (const float*)d_in[1];
    const float* S2 = (const float*)d_in[2];
    float* out = (float*)d_out;

    const int smem = (TILE_R * 8 * GPAD + TILE_R * F_S) * (int)sizeof(float2)
                   + (T_S + 4 * T_S + THREADS + 8) * (int)sizeof(float);
    cudaFuncSetAttribute(k_net, cudaFuncAttributeMaxDynamicSharedMemorySize, smem);

    const int n = B_TOTAL * F_S * 2;
    k_max1<<<256, 256>>>(u, n);
    k_max2<<<1, 256>>>();
    k_tw<<<1, 64>>>();
    k_net<<<GRID, THREADS, smem>>>(u, S1, S2, out);

    (void)in_sizes; (void)n_in; (void)out_size;
}